// round 12
// baseline (speedup 1.0000x reference)
#include <cuda_runtime.h>
#include <cuda_bf16.h>

#define PAD_VAL  -1000.0f
#define ROW      4096
#define NROWS    1024
#define SEGF     1024          // floats per segment
#define NSEG     4             // segments per row
#define NCHK     256           // owned 4-float chunks per segment
#define HALO     16            // halo chunks (next 64 floats)
#define RPB      4             // rows per block (per-thread ILP)
#define PLANE    (NCHK + HALO) // 272
#define M4LEN    268           // M4[c] defined for c in [0, 268)
#define THREADS  256

// out[i] = relu( max_{j=1..64} h[i+j]-j  -  h[i] ),  right-pad -1000.
// Segment-local frame G[t'] = h[t'] - t' (t' <= 1087):
//   out[t'] = relu( max G[t'+1 .. t'+64] - G[t'] )
// Thread t owns chunk t (4 floats, coalesced float4) in 4 rows.
// Window = own suffix + chunks t+1..t+15 + prefix of chunk t+16.
// Two-level smem range-max: M4[c] = max chunk-maxes c..c+3, so the middle
// term is 4 LDS (t+1, t+5, t+9, t+12; overlap harmless) instead of 15.
__global__ __launch_bounds__(THREADS, 7) void h2i_kernel(
    const float* __restrict__ hf, float* __restrict__ out)
{
    const int t   = threadIdx.x;
    const int rg  = blockIdx.x >> 2;            // row group
    const int seg = blockIdx.x & (NSEG - 1);
    const size_t base0 = ((size_t)rg * RPB) * ROW + (size_t)seg * SEGF;

    __shared__ float sP0[RPB][PLANE];
    __shared__ float sP1[RPB][PLANE];
    __shared__ float sP2[RPB][PLANE];
    __shared__ float sP3[RPB][PLANE];
    __shared__ float sM4[RPB][M4LEN];

    // ---- front-batched loads: 4 main + (threads<64) 1 halo ----
    float4 a[RPB];
    #pragma unroll
    for (int j = 0; j < RPB; j++)
        a[j] = ((const float4*)(hf + base0 + (size_t)j * ROW))[t];

    float4 hr;
    const int hj = t >> 4, ht = t & 15;         // halo: row, chunk-in-halo
    if (t < 64) {
        if (seg < NSEG - 1)
            hr = ((const float4*)(hf + base0 + (size_t)hj * ROW + SEGF))[ht];
        else
            hr = make_float4(PAD_VAL, PAD_VAL, PAD_VAL, PAD_VAL);
    }

    // ---- reindex to G-frame + prefix maxes -> summary planes ----
    const float tb = (float)(4 * t);
    float g[RPB][4];
    #pragma unroll
    for (int j = 0; j < RPB; j++) {
        g[j][0] = a[j].x - tb;
        g[j][1] = a[j].y - (tb + 1.0f);
        g[j][2] = a[j].z - (tb + 2.0f);
        g[j][3] = a[j].w - (tb + 3.0f);
        const float p1 = fmaxf(g[j][0], g[j][1]);
        const float p2 = fmaxf(p1, g[j][2]);
        const float p3 = fmaxf(p2, g[j][3]);
        sP0[j][t] = g[j][0]; sP1[j][t] = p1; sP2[j][t] = p2; sP3[j][t] = p3;
    }
    if (t < 64) {
        const float hb = (float)(SEGF + 4 * ht);
        const float h0 = hr.x - hb,          h1 = hr.y - (hb + 1.0f);
        const float h2 = hr.z - (hb + 2.0f), h3 = hr.w - (hb + 3.0f);
        const float q1 = fmaxf(h0, h1), q2 = fmaxf(q1, h2), q3 = fmaxf(q2, h3);
        sP0[hj][NCHK + ht] = h0; sP1[hj][NCHK + ht] = q1;
        sP2[hj][NCHK + ht] = q2; sP3[hj][NCHK + ht] = q3;
    }
    __syncthreads();

    // ---- build level-2 plane: M4[c] = max(M[c..c+3]) for c < 268 ----
    #pragma unroll
    for (int j = 0; j < RPB; j++) {
        float m4 = fmaxf(fmaxf(sP3[j][t],     sP3[j][t + 1]),
                         fmaxf(sP3[j][t + 2], sP3[j][t + 3]));
        sM4[j][t] = m4;
    }
    if (t < M4LEN - NCHK) {                     // threads 0..11: halo part
        const int c = NCHK + t;
        #pragma unroll
        for (int j = 0; j < RPB; j++) {
            float m4 = fmaxf(fmaxf(sP3[j][c],     sP3[j][c + 1]),
                             fmaxf(sP3[j][c + 2], sP3[j][c + 3]));
            sM4[j][c] = m4;
        }
    }
    __syncthreads();

    // ---- combine + store, 4 rows back-to-back ----
    #pragma unroll
    for (int j = 0; j < RPB; j++) {
        // middle chunks t+1..t+15 via 4 overlapping M4 lookups
        const float mid = fmaxf(fmaxf(sM4[j][t + 1], sM4[j][t + 5]),
                                fmaxf(sM4[j][t + 9], sM4[j][t + 12]));

        const float B0 = sP0[j][t + 16];
        const float B1 = sP1[j][t + 16];
        const float B2 = sP2[j][t + 16];
        const float B3 = sP3[j][t + 16];

        const float suf2 = g[j][3];
        const float suf1 = fmaxf(g[j][2], suf2);
        const float suf0 = fmaxf(g[j][1], suf1);

        float w, r0, r1, r2, r3;
        w = fmaxf(fmaxf(suf0, mid), B0); r0 = fmaxf(w - g[j][0], 0.0f);
        w = fmaxf(fmaxf(suf1, mid), B1); r1 = fmaxf(w - g[j][1], 0.0f);
        w = fmaxf(fmaxf(suf2, mid), B2); r2 = fmaxf(w - g[j][2], 0.0f);
        w = fmaxf(mid, B3);              r3 = fmaxf(w - g[j][3], 0.0f);

        ((float4*)(out + base0 + (size_t)j * ROW))[t] = make_float4(r0, r1, r2, r3);
    }
}

extern "C" void kernel_launch(void* const* d_in, const int* in_sizes, int n_in,
                              void* d_out, int out_size)
{
    const float* hf  = (const float*)d_in[0];
    float*       out = (float*)d_out;
    (void)in_sizes; (void)n_in; (void)out_size;
    // 7 blocks x ~21.7KB smem per SM needs the max smem carveout.
    cudaFuncSetAttribute(h2i_kernel,
                         cudaFuncAttributePreferredSharedMemoryCarveout,
                         cudaSharedmemCarveoutMaxShared);
    // 256 row-groups x 4 segments = 1024 blocks; 7/SM -> single wave
    h2i_kernel<<<(NROWS / RPB) * NSEG, THREADS>>>(hf, out);
}

// round 13
// speedup vs baseline: 1.0586x; 1.0586x over previous
#include <cuda_runtime.h>
#include <cuda_bf16.h>
#include <cstdint>

#define PAD_VAL  -1000.0f
#define ROW      4096
#define NROWS    1024
#define SEGF     1024          // owned floats per segment
#define NSEG     4
#define NCHK     256           // owned 4-float chunks
#define HALO     16            // halo chunks (next 64 floats)
#define RPB      4             // rows per block
#define RAWF     (SEGF + 64)   // 1088 floats per row incl. halo
#define PLANE    (NCHK + HALO) // 272
#define THREADS  256

// out[i] = relu( max_{j=1..64} h[i+j]-j - h[i] ), right-pad -1000.
// Segment-local frame G[t'] = h[t'] - t':
//   out[t'] = relu( max G[t'+1..t'+64] - G[t'] )
// Data path: thread 0 issues 4 cp.async.bulk (one per row, 4352B incl. halo)
// into smem against ONE mbarrier (expect_tx = total). No register LDG
// front-batching — warps wait once on the mbarrier, then compute from smem:
//   own chunk  : 1 LDS.128
//   mid        : 15 scalar LDS of the chunk-max plane
//   B-prefix   : 1 LDS.128 of chunk t+16 raw + 3 fmax (no prefix planes)
__global__ __launch_bounds__(THREADS, 7) void h2i_kernel(
    const float* __restrict__ hf, float* __restrict__ out)
{
    const int t   = threadIdx.x;
    const int rg  = blockIdx.x >> 2;
    const int seg = blockIdx.x & (NSEG - 1);
    const size_t base0 = ((size_t)rg * RPB) * ROW + (size_t)seg * SEGF;
    const bool last = (seg == NSEG - 1);

    __shared__ alignas(16) float raw[RPB][RAWF];
    __shared__ float sM[RPB][PLANE];
    __shared__ alignas(8) uint64_t mbar;

    // smem addresses (shared-window) for PTX
    uint32_t mbar_a;
    asm volatile("{ .reg .u64 x; cvta.to.shared.u64 x, %1; cvt.u32.u64 %0, x; }"
                 : "=r"(mbar_a) : "l"(&mbar));

    if (t == 0)
        asm volatile("mbarrier.init.shared.b64 [%0], 1;" :: "r"(mbar_a) : "memory");
    __syncthreads();

    const uint32_t row_bytes = last ? SEGF * 4u : RAWF * 4u;
    if (t == 0) {
        asm volatile("mbarrier.arrive.expect_tx.shared.b64 _, [%0], %1;"
                     :: "r"(mbar_a), "r"(row_bytes * RPB) : "memory");
        #pragma unroll
        for (int j = 0; j < RPB; j++) {
            uint32_t dst;
            asm volatile("{ .reg .u64 x; cvta.to.shared.u64 x, %1; cvt.u32.u64 %0, x; }"
                         : "=r"(dst) : "l"(&raw[j][0]));
            const float* src = hf + base0 + (size_t)j * ROW;
            asm volatile(
                "cp.async.bulk.shared::cta.global.mbarrier::complete_tx::bytes "
                "[%0], [%1], %2, [%3];"
                :: "r"(dst), "l"(src), "r"(row_bytes), "r"(mbar_a) : "memory");
        }
    }

    // sentinel halo for the last segment (different smem region than the copy)
    if (last) {                                  // 256 floats, one per thread
        const int j = t >> 6, idx = t & 63;
        raw[j][SEGF + idx] = PAD_VAL;
    }

    // ---- wait for all 4 bulk copies (acquire orders the smem reads below) ----
    {
        uint32_t done;
        asm volatile(
            "{\n\t.reg .pred p;\n\t"
            "mbarrier.try_wait.parity.acquire.cta.shared::cta.b64 p, [%1], 0;\n\t"
            "selp.b32 %0, 1, 0, p;\n\t}"
            : "=r"(done) : "r"(mbar_a) : "memory");
        while (!done) {
            asm volatile(
                "{\n\t.reg .pred p;\n\t"
                "mbarrier.try_wait.parity.acquire.cta.shared::cta.b64 p, [%1], 0, 0x989680;\n\t"
                "selp.b32 %0, 1, 0, p;\n\t}"
                : "=r"(done) : "r"(mbar_a) : "memory");
        }
    }
    __syncthreads();                             // all lanes past wait + halo fill

    // ---- per-row: own chunk from smem, G-frame, chunk-max plane ----
    const float tb = (float)(4 * t);
    float g[RPB][4];
    #pragma unroll
    for (int j = 0; j < RPB; j++) {
        float4 a = ((const float4*)&raw[j][0])[t];
        g[j][0] = a.x - tb;
        g[j][1] = a.y - (tb + 1.0f);
        g[j][2] = a.z - (tb + 2.0f);
        g[j][3] = a.w - (tb + 3.0f);
        sM[j][t] = fmaxf(fmaxf(g[j][0], g[j][1]), fmaxf(g[j][2], g[j][3]));
    }
    if (t < 64) {                                // halo chunk maxes
        const int j2 = t >> 4, ht = t & 15;
        float4 a = ((const float4*)&raw[j2][0])[NCHK + ht];
        const float hb = (float)(SEGF + 4 * ht);
        const float m = fmaxf(fmaxf(a.x - hb,          a.y - (hb + 1.0f)),
                              fmaxf(a.z - (hb + 2.0f), a.w - (hb + 3.0f)));
        sM[j2][NCHK + ht] = m;
    }
    __syncthreads();

    // ---- combine + store ----
    #pragma unroll
    for (int j = 0; j < RPB; j++) {
        float mid = sM[j][t + 1];
        #pragma unroll
        for (int k = 2; k <= 15; k++)
            mid = fmaxf(mid, sM[j][t + k]);

        // B-prefix of chunk t+16 straight from raw
        float4 b = ((const float4*)&raw[j][0])[t + 16];
        const float bb = tb + 64.0f;
        const float B0 = b.x - bb;
        const float B1 = fmaxf(B0, b.y - (bb + 1.0f));
        const float B2 = fmaxf(B1, b.z - (bb + 2.0f));
        const float B3 = fmaxf(B2, b.w - (bb + 3.0f));

        const float suf2 = g[j][3];
        const float suf1 = fmaxf(g[j][2], suf2);
        const float suf0 = fmaxf(g[j][1], suf1);

        float w, r0, r1, r2, r3;
        w = fmaxf(fmaxf(suf0, mid), B0); r0 = fmaxf(w - g[j][0], 0.0f);
        w = fmaxf(fmaxf(suf1, mid), B1); r1 = fmaxf(w - g[j][1], 0.0f);
        w = fmaxf(fmaxf(suf2, mid), B2); r2 = fmaxf(w - g[j][2], 0.0f);
        w = fmaxf(mid, B3);              r3 = fmaxf(w - g[j][3], 0.0f);

        ((float4*)(out + base0 + (size_t)j * ROW))[t] = make_float4(r0, r1, r2, r3);
    }
}

extern "C" void kernel_launch(void* const* d_in, const int* in_sizes, int n_in,
                              void* d_out, int out_size)
{
    const float* hf  = (const float*)d_in[0];
    float*       out = (float*)d_out;
    (void)in_sizes; (void)n_in; (void)out_size;
    cudaFuncSetAttribute(h2i_kernel,
                         cudaFuncAttributePreferredSharedMemoryCarveout,
                         cudaSharedmemCarveoutMaxShared);
    // 256 row-groups x 4 segments = 1024 blocks; 7/SM -> single wave
    h2i_kernel<<<(NROWS / RPB) * NSEG, THREADS>>>(hf, out);
}